// round 14
// baseline (speedup 1.0000x reference)
#include <cuda_runtime.h>
#include <cstdint>

// FlexMoERouter: logits[8192,16] = x*Wg + image*Wi + text*Wt + audio*Wa + biases
// -> softmax -> top4 (renorm) -> aux loss.
// Output (float32): [0,32768) idx as float, [32768,65536) probs, [65536] aux.

#define B_    4
#define S_    2048
#define H_    1024
#define E_    16
#define TOPK  4
#define NTOK  (B_ * S_)        // 8192
#define TPB   64               // tokens per block
#define NTHR  512
#define NWRP  16               // 16 warps = 16 k-classes
#define NBLK  (NTOK / TPB)     // 128 blocks (one per SM)
#define KC    256              // k floats per stage -> 1KB contiguous per token row
#define NSTG  16               // 4 modalities x 4 k-chunks
#define NBUF  2
#define RSTR  260              // smem row stride (floats): 65x16B granules (odd)
#define RPB   (TPB + E_)       // 80 rows per buffer (64 x + 16 W)

#define BUF(b)  ((b) * (RPB * RSTR))
#define SMEMF   (NBUF * RPB * RSTR)          // 41600 floats
#define SMEMB   (SMEMF * 4)                  // 166400 bytes

__device__ float g_Wt[4][E_][H_];       // transposed weights: g_Wt[m][e][k]
__device__ float g_partial[NBLK][E_];   // per-block sum of router_probs per expert
__device__ int   g_count;               // zero-init; self-resets each launch

__device__ __forceinline__ void fma2(unsigned long long& acc,
                                     unsigned long long a, unsigned long long b)
{
    asm("fma.rn.f32x2 %0, %1, %2, %0;" : "+l"(acc) : "l"(a), "l"(b));
}
__device__ __forceinline__ float fma2_lo(unsigned long long v) {
    return __uint_as_float((unsigned)(v & 0xffffffffull));
}
__device__ __forceinline__ float fma2_hi(unsigned long long v) {
    return __uint_as_float((unsigned)(v >> 32));
}
__device__ __forceinline__ void cp16(uint32_t dst_s, const float* src)
{
    asm volatile("cp.async.cg.shared.global [%0], [%1], 16;" :: "r"(dst_s), "l"(src));
}
__device__ __forceinline__ void cp_commit() { asm volatile("cp.async.commit_group;"); }
__device__ __forceinline__ void cp_wait1()  { asm volatile("cp.async.wait_group 1;"); }
__device__ __forceinline__ void cp_wait0()  { asm volatile("cp.async.wait_group 0;"); }

__device__ __forceinline__ float4 f4_add(float4 a, float4 b) {
    return make_float4(a.x + b.x, a.y + b.y, a.z + b.z, a.w + b.w);
}
__device__ __forceinline__ float4 f4_shfl_xor(float4 v, int m) {
    float4 r;
    r.x = __shfl_xor_sync(0xffffffffu, v.x, m);
    r.y = __shfl_xor_sync(0xffffffffu, v.y, m);
    r.z = __shfl_xor_sync(0xffffffffu, v.z, m);
    r.w = __shfl_xor_sync(0xffffffffu, v.w, m);
    return r;
}

// Pre-kernel: transpose W[1024][16] -> g_Wt[m][16][1024].
__global__ void transpose_W(const float* __restrict__ Wg, const float* __restrict__ Wi,
                            const float* __restrict__ Wt, const float* __restrict__ Wa)
{
    const float* Ws[4] = {Wg, Wi, Wt, Wa};
    const int idx = blockIdx.x * 256 + threadIdx.x;   // 0..16383
    const int m = idx >> 12;
    const int r = idx & 4095;
    const int k = r >> 2;
    const int ec = r & 3;
    float4 v = reinterpret_cast<const float4*>(Ws[m])[r];
    g_Wt[m][ec * 4 + 0][k] = v.x;
    g_Wt[m][ec * 4 + 1][k] = v.y;
    g_Wt[m][ec * 4 + 2][k] = v.z;
    g_Wt[m][ec * 4 + 3][k] = v.w;
}

__global__ __launch_bounds__(NTHR, 1)
void router_main(const float* __restrict__ x,   const float* __restrict__ img,
                 const float* __restrict__ txt, const float* __restrict__ aud,
                 const float* __restrict__ bg,  const float* __restrict__ bi,
                 const float* __restrict__ bt,  const float* __restrict__ ba,
                 float* __restrict__ out)
{
    extern __shared__ float sm[];
    __shared__ float  sl[TPB][E_];       // logits (bias included)
    __shared__ float  bsum[E_];
    __shared__ float  wpart[2][E_];
    __shared__ float4 red_smf[8][4];
    __shared__ float  red_sterm[4];
    __shared__ int    s_isLast;

    const int tid  = threadIdx.x;
    const int lane = tid & 31;
    const int warp = tid >> 5;             // 0..15 = k-class (granule g % 16 == warp)
    const int tokB0 = blockIdx.x * TPB;

    const float* xs_[4] = {x, img, txt, aud};
    const uint32_t smem_base = (uint32_t)__cvta_generic_to_shared(sm);

    if (tid < E_) bsum[tid] = bg[tid] + bi[tid] + bt[tid] + ba[tid];

    // Two tokens per thread: lane and lane+32. acc over (even-k, odd-k) pairs.
    unsigned long long acc0[E_], acc1[E_];
#pragma unroll
    for (int e = 0; e < E_; e++) { acc0[e] = 0ull; acc1[e] = 0ull; }

    // ---- async stage issue: 64 x-rows + 16 W-rows, 1KB CONTIGUOUS per row ----
    // Consecutive warps cover a full row back-to-back: idx>>6 = row, idx&63 = granule.
    auto issue = [&](int s) {
        const int m  = s >> 2;
        const int kc = (s & 3) * KC;
        const int b  = s & (NBUF - 1);
        const uint32_t bd = smem_base + BUF(b) * 4;
        const float* xsrc = xs_[m] + (size_t)tokB0 * H_ + kc;
#pragma unroll
        for (int j = 0; j < 8; j++) {
            const int idx = tid + NTHR * j;        // 0..4095
            const int row = idx >> 6;              // 0..63
            const int g   = idx & 63;              // 0..63 (1KB per row, contiguous)
            cp16(bd + (uint32_t)(row * RSTR + g * 4) * 4, xsrc + row * H_ + g * 4);
        }
        const float* wsrc = &g_Wt[m][0][kc];
#pragma unroll
        for (int j = 0; j < 2; j++) {
            const int idx = tid + NTHR * j;        // 0..1023
            const int row = idx >> 6;              // 0..15
            const int g   = idx & 63;
            cp16(bd + (uint32_t)((TPB + row) * RSTR + g * 4) * 4, wsrc + row * H_ + g * 4);
        }
        cp_commit();
    };

    issue(0); issue(1);
#pragma unroll 1
    for (int s = 0; s < NSTG; s++) {
        if (s == NSTG - 1) cp_wait0(); else cp_wait1();
        __syncthreads();                  // stage s data visible to all

        const int b = s & (NBUF - 1);
        const float* xb = sm + BUF(b);
        const float* wb = xb + TPB * RSTR;
        const ulonglong2* xr0 = reinterpret_cast<const ulonglong2*>(xb + lane * RSTR);
        const ulonglong2* xr1 = reinterpret_cast<const ulonglong2*>(xb + (lane + 32) * RSTR);

#pragma unroll
        for (int i = 0; i < 4; i++) {
            const int o = warp + 16 * i;           // this warp's granule in stage
            const ulonglong2 xv0 = xr0[o];
            const ulonglong2 xv1 = xr1[o];
#pragma unroll
            for (int e = 0; e < E_; e++) {
                const ulonglong2 wv =
                    reinterpret_cast<const ulonglong2*>(wb + e * RSTR)[o];  // warp-uniform
                fma2(acc0[e], xv0.x, wv.x);
                fma2(acc0[e], xv0.y, wv.y);
                fma2(acc1[e], xv1.x, wv.x);
                fma2(acc1[e], xv1.y, wv.y);
            }
        }
        __syncthreads();                  // buf b fully consumed -> safe to overwrite
        if (s + 2 < NSTG) issue(s + 2);
    }

    // ---- cross-warp (k) reduction via smem: red[wk][tok][e] (16*64*16 = 64KB) ----
    float* red = sm;
    {
        float4* dst0 = reinterpret_cast<float4*>(red + warp * (TPB * E_) + lane * E_);
        float4* dst1 = reinterpret_cast<float4*>(red + warp * (TPB * E_) + (lane + 32) * E_);
#pragma unroll
        for (int q = 0; q < 4; q++) {
            dst0[q] = make_float4(
                fma2_lo(acc0[q * 4 + 0]) + fma2_hi(acc0[q * 4 + 0]),
                fma2_lo(acc0[q * 4 + 1]) + fma2_hi(acc0[q * 4 + 1]),
                fma2_lo(acc0[q * 4 + 2]) + fma2_hi(acc0[q * 4 + 2]),
                fma2_lo(acc0[q * 4 + 3]) + fma2_hi(acc0[q * 4 + 3]));
            dst1[q] = make_float4(
                fma2_lo(acc1[q * 4 + 0]) + fma2_hi(acc1[q * 4 + 0]),
                fma2_lo(acc1[q * 4 + 1]) + fma2_hi(acc1[q * 4 + 1]),
                fma2_lo(acc1[q * 4 + 2]) + fma2_hi(acc1[q * 4 + 2]),
                fma2_lo(acc1[q * 4 + 3]) + fma2_hi(acc1[q * 4 + 3]));
        }
    }
    __syncthreads();

    if (tid < 256) {   // each sums 16 k-partials for (token, expert-quad)
        const int t = tid >> 2;
        const int q = tid & 3;
        float4 s4 = make_float4(0.f, 0.f, 0.f, 0.f);
#pragma unroll
        for (int w = 0; w < NWRP; w++)
            s4 = f4_add(s4, reinterpret_cast<const float4*>(
                                red + w * (TPB * E_) + t * E_ + q * 4)[0]);
        const float4 bq = reinterpret_cast<const float4*>(bsum)[q];
        reinterpret_cast<float4*>(&sl[t][q * 4])[0] = f4_add(s4, bq);
    }
    __syncthreads();

    // ---- epilogue: threads 0..63, one token each ----
    if (tid < TPB) {
        const int g = blockIdx.x * TPB + tid;
        float p[E_], q[E_];
        float mx = -1e30f;
#pragma unroll
        for (int e = 0; e < E_; e++) {
            float l = sl[tid][e];
            p[e] = l;
            mx = fmaxf(mx, l);
        }
        float ssum = 0.0f;
#pragma unroll
        for (int e = 0; e < E_; e++) { p[e] = expf(p[e] - mx); ssum += p[e]; }
        const float inv = 1.0f / ssum;
#pragma unroll
        for (int e = 0; e < E_; e++) { p[e] *= inv; q[e] = p[e]; }

        float tp[TOPK]; int ti[TOPK]; float tsum = 0.0f;
#pragma unroll
        for (int j = 0; j < TOPK; j++) {
            float best = -1.0f; int bidx = 0;
#pragma unroll
            for (int e = 0; e < E_; e++)
                if (p[e] > best) { best = p[e]; bidx = e; }
            tp[j] = best; ti[j] = bidx; tsum += best;
            p[bidx] = -2.0f;
        }
        const float tinv = 1.0f / tsum;
        float4* oi = reinterpret_cast<float4*>(out + (size_t)g * TOPK);
        float4* op = reinterpret_cast<float4*>(out + (size_t)NTOK * TOPK + (size_t)g * TOPK);
        *oi = make_float4((float)ti[0], (float)ti[1], (float)ti[2], (float)ti[3]);
        *op = make_float4(tp[0] * tinv, tp[1] * tinv, tp[2] * tinv, tp[3] * tinv);

        // per-expert prob sums (warp 0: tokens 0-31, warp 1: 32-63)
#pragma unroll
        for (int e = 0; e < E_; e++) {
            float v = q[e];
            v += __shfl_xor_sync(0xffffffffu, v, 16);
            v += __shfl_xor_sync(0xffffffffu, v, 8);
            v += __shfl_xor_sync(0xffffffffu, v, 4);
            v += __shfl_xor_sync(0xffffffffu, v, 2);
            v += __shfl_xor_sync(0xffffffffu, v, 1);
            if (lane == 0) wpart[warp][e] = v;
        }
    }
    __syncthreads();
    if (tid < E_)
        g_partial[blockIdx.x][tid] = wpart[0][tid] + wpart[1][tid];
    __syncthreads();

    // ---- last block reduces g_partial -> aux loss (fixed order, deterministic) ----
    if (tid == 0) {
        __threadfence();
        int old = atomicAdd(&g_count, 1);
        s_isLast = (old == NBLK - 1);
    }
    __syncthreads();
    if (s_isLast && tid < 256) {
        __threadfence();
        // g_partial = 128 x 16 = 512 float4
        const float4* gp4 = reinterpret_cast<const float4*>(&g_partial[0][0]);
        float4 v = f4_add(gp4[tid], gp4[tid + 256]);
        v = f4_add(v, f4_shfl_xor(v, 4));
        v = f4_add(v, f4_shfl_xor(v, 8));
        v = f4_add(v, f4_shfl_xor(v, 16));
        if (lane < 4) red_smf[warp][lane] = v;
        __syncwarp();
    }
    __syncthreads();
    if (s_isLast) {
        if (tid < 4) {
            float4 t = red_smf[0][tid];
#pragma unroll
            for (int w = 1; w < 8; w++) t = f4_add(t, red_smf[w][tid]);
            const float invn = 1.0f / (float)NTOK;
            float s = 0.0f, pe;
            pe = t.x * invn; s += pe * logf(pe * (float)E_ + 1e-9f);
            pe = t.y * invn; s += pe * logf(pe * (float)E_ + 1e-9f);
            pe = t.z * invn; s += pe * logf(pe * (float)E_ + 1e-9f);
            pe = t.w * invn; s += pe * logf(pe * (float)E_ + 1e-9f);
            red_sterm[tid] = s;
        }
        __syncthreads();
        if (tid == 0) {
            out[(size_t)NTOK * TOPK * 2] = red_sterm[0] + red_sterm[1]
                                         + red_sterm[2] + red_sterm[3];
            g_count = 0;                 // reset for next graph replay
        }
    }
}

extern "C" void kernel_launch(void* const* d_in, const int* in_sizes, int n_in,
                              void* d_out, int out_size)
{
    (void)in_sizes; (void)n_in; (void)out_size;
    const float* x   = (const float*)d_in[0];
    const float* img = (const float*)d_in[1];
    const float* txt = (const float*)d_in[2];
    const float* aud = (const float*)d_in[3];
    const float* Wg  = (const float*)d_in[4];
    const float* bg  = (const float*)d_in[5];
    const float* Wi  = (const float*)d_in[6];
    const float* bi  = (const float*)d_in[7];
    const float* Wt  = (const float*)d_in[8];
    const float* bt  = (const float*)d_in[9];
    const float* Wa  = (const float*)d_in[10];
    const float* ba  = (const float*)d_in[11];
    float* out = (float*)d_out;

    cudaFuncSetAttribute(router_main, cudaFuncAttributeMaxDynamicSharedMemorySize, SMEMB);

    transpose_W<<<64, 256>>>(Wg, Wi, Wt, Wa);
    router_main<<<NBLK, NTHR, SMEMB>>>(x, img, txt, aud, bg, bi, bt, ba, out);
}

// round 15
// speedup vs baseline: 1.3031x; 1.3031x over previous
#include <cuda_runtime.h>
#include <cstdint>

// FlexMoERouter: logits[8192,16] = x*Wg + image*Wi + text*Wt + audio*Wa + biases
// -> softmax -> top4 (renorm) -> aux loss.
// Output (float32): [0,32768) idx as float, [32768,65536) probs, [65536] aux.

#define B_    4
#define S_    2048
#define H_    1024
#define E_    16
#define TOPK  4
#define NTOK  (B_ * S_)        // 8192
#define TPB   32               // tokens per block
#define NTHR  256
#define NWRP  8                // 8 warps = 8 k-classes, lane = token
#define NBLK  (NTOK / TPB)     // 256 blocks -> 2 CTAs/SM (decoupled barriers)
#define KC    128              // k floats per stage
#define NSTG  32               // 4 modalities x 8 k-chunks
#define NBUF  4
#define RSTR  132              // smem row stride (floats): 33x16B granules (odd)
#define RPB   (TPB + E_)       // 48 rows per buffer (32 x + 16 W)

#define BUF(b)  ((b) * (RPB * RSTR))
#define SMEMF   (NBUF * RPB * RSTR)          // 25344 floats
#define SMEMB   (SMEMF * 4)                  // 101376 bytes per CTA (x2 CTAs = 203KB/SM)

__device__ float g_Wt[4][E_][H_];       // transposed weights: g_Wt[m][e][k]
__device__ float g_partial[NBLK][E_];   // per-block sum of router_probs per expert
__device__ int   g_count;               // zero-init; self-resets each launch

__device__ __forceinline__ void fma2(unsigned long long& acc,
                                     unsigned long long a, unsigned long long b)
{
    asm("fma.rn.f32x2 %0, %1, %2, %0;" : "+l"(acc) : "l"(a), "l"(b));
}
__device__ __forceinline__ float fma2_lo(unsigned long long v) {
    return __uint_as_float((unsigned)(v & 0xffffffffull));
}
__device__ __forceinline__ float fma2_hi(unsigned long long v) {
    return __uint_as_float((unsigned)(v >> 32));
}
__device__ __forceinline__ void cp16(uint32_t dst_s, const float* src)
{
    asm volatile("cp.async.cg.shared.global [%0], [%1], 16;" :: "r"(dst_s), "l"(src));
}
__device__ __forceinline__ void cp_commit() { asm volatile("cp.async.commit_group;"); }
__device__ __forceinline__ void cp_wait2()  { asm volatile("cp.async.wait_group 2;"); }
__device__ __forceinline__ void cp_wait0()  { asm volatile("cp.async.wait_group 0;"); }

__device__ __forceinline__ float4 f4_add(float4 a, float4 b) {
    return make_float4(a.x + b.x, a.y + b.y, a.z + b.z, a.w + b.w);
}
__device__ __forceinline__ float4 f4_shfl_xor(float4 v, int m) {
    float4 r;
    r.x = __shfl_xor_sync(0xffffffffu, v.x, m);
    r.y = __shfl_xor_sync(0xffffffffu, v.y, m);
    r.z = __shfl_xor_sync(0xffffffffu, v.z, m);
    r.w = __shfl_xor_sync(0xffffffffu, v.w, m);
    return r;
}

// Pre-kernel: transpose W[1024][16] -> g_Wt[m][16][1024].
__global__ void transpose_W(const float* __restrict__ Wg, const float* __restrict__ Wi,
                            const float* __restrict__ Wt, const float* __restrict__ Wa)
{
    const float* Ws[4] = {Wg, Wi, Wt, Wa};
    const int idx = blockIdx.x * 256 + threadIdx.x;   // 0..16383
    const int m = idx >> 12;
    const int r = idx & 4095;
    const int k = r >> 2;
    const int ec = r & 3;
    float4 v = reinterpret_cast<const float4*>(Ws[m])[r];
    g_Wt[m][ec * 4 + 0][k] = v.x;
    g_Wt[m][ec * 4 + 1][k] = v.y;
    g_Wt[m][ec * 4 + 2][k] = v.z;
    g_Wt[m][ec * 4 + 3][k] = v.w;
}

__global__ __launch_bounds__(NTHR, 2)
void router_main(const float* __restrict__ x,   const float* __restrict__ img,
                 const float* __restrict__ txt, const float* __restrict__ aud,
                 const float* __restrict__ bg,  const float* __restrict__ bi,
                 const float* __restrict__ bt,  const float* __restrict__ ba,
                 float* __restrict__ out)
{
    extern __shared__ float sm[];
    __shared__ float  sl[TPB][E_];       // logits (bias included)
    __shared__ float  bsum[E_];
    __shared__ float4 red_smf[8][4];
    __shared__ float  red_sterm[4];
    __shared__ int    s_isLast;

    const int tid  = threadIdx.x;
    const int lane = tid & 31;           // = token within block
    const int warp = tid >> 5;           // 0..7 = k-class (granule g % 8 == warp)
    const int tokB0 = blockIdx.x * TPB;

    const float* xs_[4] = {x, img, txt, aud};
    const uint32_t smem_base = (uint32_t)__cvta_generic_to_shared(sm);

    if (tid < E_) bsum[tid] = bg[tid] + bi[tid] + bt[tid] + ba[tid];

    // One token per thread (token = lane); acc over (even-k, odd-k) pairs.
    unsigned long long acc[E_];
#pragma unroll
    for (int e = 0; e < E_; e++) acc[e] = 0ull;

    // ---- async stage issue: 32 x-rows + 16 W-rows, 512B per row ----
    auto issue = [&](int s) {
        const int m  = s >> 3;
        const int kc = (s & 7) * KC;
        const int b  = s & (NBUF - 1);
        const uint32_t bd = smem_base + BUF(b) * 4;
        const float* xsrc = xs_[m] + (size_t)tokB0 * H_ + kc;
#pragma unroll
        for (int j = 0; j < 4; j++) {
            const int idx = tid + NTHR * j;        // 0..1023
            const int row = idx >> 5;              // 0..31
            const int g   = idx & 31;
            cp16(bd + (uint32_t)(row * RSTR + g * 4) * 4, xsrc + row * H_ + g * 4);
        }
        const float* wsrc = &g_Wt[m][0][kc];
#pragma unroll
        for (int j = 0; j < 2; j++) {
            const int idx = tid + NTHR * j;        // 0..511
            const int row = idx >> 5;              // 0..15
            const int g   = idx & 31;
            cp16(bd + (uint32_t)((TPB + row) * RSTR + g * 4) * 4, wsrc + row * H_ + g * 4);
        }
        cp_commit();
    };

    issue(0); issue(1); issue(2);
#pragma unroll 1
    for (int s = 0; s < NSTG; s++) {
        if (s >= NSTG - 3) cp_wait0(); else cp_wait2();
        __syncthreads();                  // stage s visible; buf (s-1)%4 drained by all
        if (s + 3 < NSTG) issue(s + 3);

        const int b = s & (NBUF - 1);
        const float* xb = sm + BUF(b);
        const float* wb = xb + TPB * RSTR;
        const ulonglong2* xr = reinterpret_cast<const ulonglong2*>(xb + lane * RSTR);

#pragma unroll
        for (int i = 0; i < 4; i++) {
            const int o = warp + 8 * i;            // this warp's granule in stage
            const ulonglong2 xv = xr[o];
#pragma unroll
            for (int e = 0; e < E_; e++) {
                const ulonglong2 wv =
                    reinterpret_cast<const ulonglong2*>(wb + e * RSTR)[o];  // warp-uniform
                fma2(acc[e], xv.x, wv.x);
                fma2(acc[e], xv.y, wv.y);
            }
        }
    }
    __syncthreads();                       // all compute done; stage bufs reusable

    // ---- cross-warp (k) reduction via smem: red[wk][tok][e] (8*32*16 = 16KB) ----
    float* red = sm;
    {
        float4* dst = reinterpret_cast<float4*>(red + warp * (TPB * E_) + lane * E_);
#pragma unroll
        for (int q = 0; q < 4; q++) {
            dst[q] = make_float4(
                fma2_lo(acc[q * 4 + 0]) + fma2_hi(acc[q * 4 + 0]),
                fma2_lo(acc[q * 4 + 1]) + fma2_hi(acc[q * 4 + 1]),
                fma2_lo(acc[q * 4 + 2]) + fma2_hi(acc[q * 4 + 2]),
                fma2_lo(acc[q * 4 + 3]) + fma2_hi(acc[q * 4 + 3]));
        }
    }
    __syncthreads();

    if (tid < TPB * 4) {   // 128 threads: each sums 8 k-partials for (token, quad)
        const int t = tid >> 2;
        const int q = tid & 3;
        float4 s4 = make_float4(0.f, 0.f, 0.f, 0.f);
#pragma unroll
        for (int w = 0; w < NWRP; w++)
            s4 = f4_add(s4, reinterpret_cast<const float4*>(
                                red + w * (TPB * E_) + t * E_ + q * 4)[0]);
        const float4 bq = reinterpret_cast<const float4*>(bsum)[q];
        reinterpret_cast<float4*>(&sl[t][q * 4])[0] = f4_add(s4, bq);
    }
    __syncthreads();

    // ---- epilogue: warp 0, one thread per token ----
    if (tid < TPB) {
        const int g = blockIdx.x * TPB + tid;
        float p[E_], q[E_];
        float mx = -1e30f;
#pragma unroll
        for (int e = 0; e < E_; e++) {
            float l = sl[tid][e];
            p[e] = l;
            mx = fmaxf(mx, l);
        }
        float ssum = 0.0f;
#pragma unroll
        for (int e = 0; e < E_; e++) { p[e] = expf(p[e] - mx); ssum += p[e]; }
        const float inv = 1.0f / ssum;
#pragma unroll
        for (int e = 0; e < E_; e++) { p[e] *= inv; q[e] = p[e]; }

        float tp[TOPK]; int ti[TOPK]; float tsum = 0.0f;
#pragma unroll
        for (int j = 0; j < TOPK; j++) {
            float best = -1.0f; int bidx = 0;
#pragma unroll
            for (int e = 0; e < E_; e++)
                if (p[e] > best) { best = p[e]; bidx = e; }
            tp[j] = best; ti[j] = bidx; tsum += best;
            p[bidx] = -2.0f;
        }
        const float tinv = 1.0f / tsum;
        float4* oi = reinterpret_cast<float4*>(out + (size_t)g * TOPK);
        float4* op = reinterpret_cast<float4*>(out + (size_t)NTOK * TOPK + (size_t)g * TOPK);
        *oi = make_float4((float)ti[0], (float)ti[1], (float)ti[2], (float)ti[3]);
        *op = make_float4(tp[0] * tinv, tp[1] * tinv, tp[2] * tinv, tp[3] * tinv);

        // per-expert prob sums across the block's 32 tokens (warp 0, fixed order)
#pragma unroll
        for (int e = 0; e < E_; e++) {
            float v = q[e];
            v += __shfl_xor_sync(0xffffffffu, v, 16);
            v += __shfl_xor_sync(0xffffffffu, v, 8);
            v += __shfl_xor_sync(0xffffffffu, v, 4);
            v += __shfl_xor_sync(0xffffffffu, v, 2);
            v += __shfl_xor_sync(0xffffffffu, v, 1);
            if (lane == 0) g_partial[blockIdx.x][e] = v;
        }
    }
    __syncthreads();

    // ---- last block reduces g_partial -> aux loss (fixed order, deterministic) ----
    if (tid == 0) {
        __threadfence();
        int old = atomicAdd(&g_count, 1);
        s_isLast = (old == NBLK - 1);
    }
    __syncthreads();
    if (s_isLast) {
        __threadfence();
        // g_partial = 256 x 16 = 1024 float4 (f&3 = expert quad, f>>2 = block)
        const float4* gp4 = reinterpret_cast<const float4*>(&g_partial[0][0]);
        float4 v = f4_add(f4_add(gp4[tid], gp4[tid + 256]),
                          f4_add(gp4[tid + 512], gp4[tid + 768]));
        v = f4_add(v, f4_shfl_xor(v, 4));
        v = f4_add(v, f4_shfl_xor(v, 8));
        v = f4_add(v, f4_shfl_xor(v, 16));
        if (lane < 4) red_smf[warp][lane] = v;     // lane == expert quad
        __syncthreads();
        if (tid < 4) {
            float4 t = red_smf[0][tid];
#pragma unroll
            for (int w = 1; w < 8; w++) t = f4_add(t, red_smf[w][tid]);
            const float invn = 1.0f / (float)NTOK;
            float s = 0.0f, pe;
            pe = t.x * invn; s += pe * logf(pe * (float)E_ + 1e-9f);
            pe = t.y * invn; s += pe * logf(pe * (float)E_ + 1e-9f);
            pe = t.z * invn; s += pe * logf(pe * (float)E_ + 1e-9f);
            pe = t.w * invn; s += pe * logf(pe * (float)E_ + 1e-9f);
            red_sterm[tid] = s;
        }
        __syncthreads();
        if (tid == 0) {
            out[(size_t)NTOK * TOPK * 2] = red_sterm[0] + red_sterm[1]
                                         + red_sterm[2] + red_sterm[3];
            g_count = 0;                 // reset for next graph replay
        }
    }
}

extern "C" void kernel_launch(void* const* d_in, const int* in_sizes, int n_in,
                              void* d_out, int out_size)
{
    (void)in_sizes; (void)n_in; (void)out_size;
    const float* x   = (const float*)d_in[0];
    const float* img = (const float*)d_in[1];
    const float* txt = (const float*)d_in[2];
    const float* aud = (const float*)d_in[3];
    const float* Wg  = (const float*)d_in[4];
    const float* bg  = (const float*)d_in[5];
    const float* Wi  = (const float*)d_in[6];
    const float* bi  = (const float*)d_in[7];
    const float* Wt  = (const float*)d_in[8];
    const float* bt  = (const float*)d_in[9];
    const float* Wa  = (const float*)d_in[10];
    const float* ba  = (const float*)d_in[11];
    float* out = (float*)d_out;

    cudaFuncSetAttribute(router_main, cudaFuncAttributeMaxDynamicSharedMemorySize, SMEMB);

    transpose_W<<<64, 256>>>(Wg, Wi, Wt, Wa);
    router_main<<<NBLK, NTHR, SMEMB>>>(x, img, txt, aud, bg, bi, bt, ba, out);
}